// round 9
// baseline (speedup 1.0000x reference)
#include <cuda_runtime.h>

#define N 4096
#define NN (N * N)
#define NITERS 300
#define NBLK 148
#define TPB 1024

__device__ float  d_K[NN];      // K = 2^(-k*C), 64MB, L2-resident
__device__ float  d_F[N];       // potentials in log2 domain
__device__ float  d_G[N];
__device__ double d_csum;
__device__ double d_emd;
__device__ float  d_k;          // log2(e)/eps
__device__ unsigned int g_bar;
__device__ unsigned int g_epoch;
__device__ unsigned int d_FmaxE[2];   // order-preserving-encoded float maxes
__device__ unsigned int d_GmaxE[2];

__device__ __forceinline__ float  ldcg(const float* p)   { return __ldcg(p); }
__device__ __forceinline__ float4 ldcg4(const float4* p) { return __ldcg(p); }

// order-preserving float<->u32 (for atomicMax over signed floats)
__device__ __forceinline__ unsigned fenc(float f) {
    unsigned u = __float_as_uint(f);
    return (u & 0x80000000u) ? ~u : (u | 0x80000000u);
}
__device__ __forceinline__ float fdec(unsigned u) {
    return (u & 0x80000000u) ? __uint_as_float(u ^ 0x80000000u)
                             : __uint_as_float(~u);
}

// ---------------------------------------------------------------- init
__global__ void k_init() {
    d_csum  = 0.0;
    d_emd   = 0.0;
    g_bar   = 0u;
    g_epoch = 0u;
    d_FmaxE[0] = 0u;  d_FmaxE[1] = 0u;
    d_GmaxE[0] = 0u;  d_GmaxE[1] = 0x80000000u;   // = fenc(0.0f): iter-0 f-pass reads Ghat=0
}

// ---------------------------------------------------------------- csum; zero F/G
__global__ void k_sum(const float* __restrict__ x, const float* __restrict__ y) {
    __shared__ float sred[8];
    int i = blockIdx.x;
    float x0 = x[3 * i], x1 = x[3 * i + 1], x2 = x[3 * i + 2];
    float xx = x0 * x0 + x1 * x1 + x2 * x2;
    float acc = 0.0f;
    for (int j = threadIdx.x; j < N; j += 256) {
        float y0 = y[3 * j], y1 = y[3 * j + 1], y2 = y[3 * j + 2];
        float yy  = y0 * y0 + y1 * y1 + y2 * y2;
        float dot = x0 * y0 + x1 * y1 + x2 * y2;
        float d2  = xx + yy - 2.0f * dot;
        acc += sqrtf(fmaxf(d2, 0.0f) + 1e-12f);
    }
    for (int o = 16; o; o >>= 1) acc += __shfl_down_sync(0xffffffffu, acc, o);
    if ((threadIdx.x & 31) == 0) sred[threadIdx.x >> 5] = acc;
    __syncthreads();
    if (threadIdx.x < 8) {
        acc = sred[threadIdx.x];
        for (int o = 4; o; o >>= 1) acc += __shfl_down_sync(0xffu, acc, o);
        if (threadIdx.x == 0) atomicAdd(&d_csum, (double)acc);
    }
    if (threadIdx.x == 0) { d_F[i] = 0.0f; d_G[i] = 0.0f; }
}

// ---------------------------------------------------------------- eps -> k
__global__ void k_eps() {
    double mean = d_csum / ((double)N * (double)N);
    d_k = (float)(1.4426950408889634 / (0.02 * mean));
}

// ---------------------------------------------------------------- build K = 2^(-k*C)
__global__ void k_buildK(const float* __restrict__ x, const float* __restrict__ y) {
    int i = blockIdx.x;
    float k = d_k;
    float x0 = x[3 * i], x1 = x[3 * i + 1], x2 = x[3 * i + 2];
    float xx = x0 * x0 + x1 * x1 + x2 * x2;
    for (int j = threadIdx.x; j < N; j += 256) {
        float y0 = y[3 * j], y1 = y[3 * j + 1], y2 = y[3 * j + 2];
        float yy  = y0 * y0 + y1 * y1 + y2 * y2;
        float dot = x0 * y0 + x1 * y1 + x2 * y2;
        float d2  = xx + yy - 2.0f * dot;
        float c   = sqrtf(fmaxf(d2, 0.0f) + 1e-12f);
        d_K[(size_t)i * N + j] = exp2f(-k * c);
    }
}

// ---------------------------------------------------------------- grid barrier (no membar/IVALL)
__device__ __forceinline__ void gsync(unsigned int& ep) {
    __syncthreads();
    if (threadIdx.x == 0) {
        unsigned int t;
        asm volatile("atom.add.release.gpu.u32 %0, [%1], 1;"
                     : "=r"(t) : "l"(&g_bar) : "memory");
        if (t == NBLK - 1) {
            g_bar = 0u;
            asm volatile("st.release.gpu.u32 [%0], %1;"
                         :: "l"(&g_epoch), "r"(ep + 1u) : "memory");
        } else {
            unsigned int v;
            do {
                asm volatile("ld.acquire.gpu.u32 %0, [%1];"
                             : "=r"(v) : "l"(&g_epoch) : "memory");
            } while (v == ep);
        }
    }
    ep++;
    __syncthreads();
}

// ---------------------------------------------------------------- persistent Sinkhorn + final P*C
__global__ void __launch_bounds__(TPB, 1) k_persist(float* __restrict__ out) {
    __shared__ float sV[N];        // staged 2^(G-Ghat) (f pass) or 2^(F-Fhat) (g pass)
    __shared__ float sr[32][33];
    __shared__ unsigned sEnc;
    const int tid = threadIdx.x;
    const int bid = blockIdx.x;
    const int wid = tid >> 5;
    const int ln  = tid & 31;
    const int frow = bid + NBLK * wid;     // round-robin row; valid if < N
    unsigned int ep = 0u;

    for (int it = 0; it < NITERS; it++) {
        const int p = it & 1;

        // ---- f pass: S_i = sum_j K_ij 2^(G_j-Ghat);  F_i = 12 - Ghat - log2(S_i)
        const float Gh = fdec(__ldcg(&d_GmaxE[p ^ 1]));
        for (int j = tid; j < N; j += TPB) sV[j] = exp2f(ldcg(&d_G[j]) - Gh);
        if (tid == 0) {
            sEnc = 0u;
            if (bid == 0) __stcg(&d_GmaxE[p], 0u);   // dead slot: rewritten by g after gsync
        }
        __syncthreads();
        if (frow < N) {
            const float4* Kr = (const float4*)(d_K + (size_t)frow * N);
            const float4* V4 = (const float4*)sV;
            float s0 = 0.f, s1 = 0.f, s2 = 0.f, s3 = 0.f;
#pragma unroll 8
            for (int t = ln; t < N / 4; t += 32) {
                float4 b = ldcg4(&Kr[t]);
                float4 g = V4[t];
                s0 = fmaf(b.x, g.x, s0);
                s1 = fmaf(b.y, g.y, s1);
                s2 = fmaf(b.z, g.z, s2);
                s3 = fmaf(b.w, g.w, s3);
            }
            float s = (s0 + s1) + (s2 + s3);
            for (int o = 16; o; o >>= 1) s += __shfl_down_sync(0xffffffffu, s, o);
            if (ln == 0) {
                float F = 12.0f - Gh - log2f(s);
                d_F[frow] = F;
                atomicMax(&sEnc, fenc(F));
            }
        }
        __syncthreads();
        if (tid == 0) atomicMax(&d_FmaxE[p], sEnc);
        gsync(ep);

        // ---- g pass: T_j = sum_i K_ij 2^(F_i-Fhat);  G_j = 12 - Fhat - log2(T_j)
        if (bid < 128) {
            const float Fh = fdec(__ldcg(&d_FmaxE[p]));
            for (int i = tid; i < N; i += TPB) sV[i] = exp2f(ldcg(&d_F[i]) - Fh);
            if (tid == 0) sEnc = 0u;
            __syncthreads();
            const int tx = ln, ty = wid;          // warp = 32 consecutive cols, row-lane ty
            const int j  = bid * 32 + tx;
            const float* Kc = d_K + j;
            float s0 = 0.f, s1 = 0.f, s2 = 0.f, s3 = 0.f;
#pragma unroll 8
            for (int i = ty; i < N; i += 128) {
                s0 = fmaf(ldcg(&Kc[(size_t)i * N]),        sV[i],      s0);
                s1 = fmaf(ldcg(&Kc[(size_t)(i + 32) * N]), sV[i + 32], s1);
                s2 = fmaf(ldcg(&Kc[(size_t)(i + 64) * N]), sV[i + 64], s2);
                s3 = fmaf(ldcg(&Kc[(size_t)(i + 96) * N]), sV[i + 96], s3);
            }
            sr[ty][tx] = (s0 + s1) + (s2 + s3);
            __syncthreads();
            float v = sr[tx][ty];                 // warp ty reduces column ty
            for (int o = 16; o; o >>= 1) v += __shfl_down_sync(0xffffffffu, v, o);
            if (tx == 0) {
                float G = 12.0f - Fh - log2f(v);
                d_G[bid * 32 + ty] = G;
                atomicMax(&sEnc, fenc(G));
            }
            __syncthreads();
            if (tid == 0) atomicMax(&d_GmaxE[p], sEnc);
        }
        if (bid == 147 && tid == 0) __stcg(&d_FmaxE[p ^ 1], 0u);   // dead slot
        gsync(ep);
    }

    // ---- final: EMD = sum P*C,  P = U V K 2^(Fh+Gh-24),  C = -log2(K)/k
    {
        const float Fh = fdec(__ldcg(&d_FmaxE[(NITERS - 1) & 1]));
        const float Gh = fdec(__ldcg(&d_GmaxE[(NITERS - 1) & 1]));
        for (int j = tid; j < N; j += TPB) sV[j] = exp2f(ldcg(&d_G[j]) - Gh);
        __syncthreads();
        float s = 0.f;
        if (frow < N) {
            const float U = exp2f(ldcg(&d_F[frow]) - Fh);
            const float4* Kr = (const float4*)(d_K + (size_t)frow * N);
            const float4* V4 = (const float4*)sV;
            float a0 = 0.f, a1 = 0.f, a2 = 0.f, a3 = 0.f;
#pragma unroll 4
            for (int t = ln; t < N / 4; t += 32) {
                float4 b = ldcg4(&Kr[t]);
                float4 g = V4[t];
                float t0 = b.x * g.x, t1 = b.y * g.y;
                float t2 = b.z * g.z, t3 = b.w * g.w;
                a0 += (b.x > 0.f) ? -t0 * __log2f(b.x) : 0.f;
                a1 += (b.y > 0.f) ? -t1 * __log2f(b.y) : 0.f;
                a2 += (b.z > 0.f) ? -t2 * __log2f(b.z) : 0.f;
                a3 += (b.w > 0.f) ? -t3 * __log2f(b.w) : 0.f;
            }
            s = U * ((a0 + a1) + (a2 + a3));
            for (int o = 16; o; o >>= 1) s += __shfl_down_sync(0xffffffffu, s, o);
        }
        if (ln == 0) sr[0][wid] = s;
        __syncthreads();
        if (tid < 32) {
            s = sr[0][tid];
            for (int o = 16; o; o >>= 1) s += __shfl_down_sync(0xffffffffu, s, o);
            if (tid == 0) atomicAdd(&d_emd, (double)s);
        }
        gsync(ep);
        if (bid == 0 && tid == 0) {
            double emd = __ldcg((const double*)&d_emd);
            out[0] = (float)(emd * exp2((double)Fh + (double)Gh - 24.0) / (double)d_k);
        }
    }
}

// ---------------------------------------------------------------- launch
extern "C" void kernel_launch(void* const* d_in, const int* in_sizes, int n_in,
                              void* d_out, int out_size) {
    const float* x = (const float*)d_in[0];
    const float* y = (const float*)d_in[1];
    float* out = (float*)d_out;

    k_init<<<1, 1>>>();
    k_sum<<<N, 256>>>(x, y);
    k_eps<<<1, 1>>>();
    k_buildK<<<N, 256>>>(x, y);
    k_persist<<<NBLK, TPB>>>(out);
}